// round 17
// baseline (speedup 1.0000x reference)
#include <cuda_runtime.h>
#include <cuda_fp16.h>
#include <cstdint>

// ---------------------------------------------------------------------------
// SpectraLoRA fused, round 16 (= R15 resubmit, static guard removed):
// per-batch effective-weight folding + fp16 mma.
//   Only 8 batches and the gate is per-batch, so:
//     W_eff[b] = W + SCALING * (gate[b] ⊙ BmT) @ A      (3.6 GF, 8 small GEMMs)
//     out      = x @ W_eff[b]^T + bias                  (58 GF, K=768 only)
//   vs R13's 67.6 GF main + 3.2 GF h-kernel. Main kernel is mma-issue-bound,
//   so -14% FLOPs ≈ -14% time.
//   Main GEMM: R13's proven 128x128 tiles, warp 64x32, 2 CTAs/SM,
//   3-stage cp.async pipeline, one __syncthreads per K-tile.
// ---------------------------------------------------------------------------

#define IN_F   768
#define OUT_F  2304
#define NBATCH 8
#define M_TOT  16384
#define NE     8
#define NR     16
#define ERDIM  128
#define GD     64
#define SCALING 2.0f

#define BK 32
#define SPADW 20                        // words per smem half-row (16 data + 4 pad)
#define NSTAGE 3
#define TILE_WORDS (128 * SPADW)        // 2560 words = 10240 B
#define SMEM_BYTES (2 * NSTAGE * TILE_WORDS * 4)   // 61440

// weff kernel: full-K (128 halves = 64 words, pad to 68) tiles
#define WE_SPADW 68
#define WE_TILE_WORDS (128 * WE_SPADW)              // 8704 words = 34816 B
#define WE_SMEM_BYTES (2 * WE_TILE_WORDS * 4)       // 69632

__device__ __half g_BmTh[OUT_F * ERDIM];            // BmT[o][j]
__device__ __half g_ATh[IN_F * ERDIM];              // A^T[i][j]
__device__ __half g_xh[(size_t)M_TOT * IN_F];       // fp16 x
__device__ __half g_Weff[(size_t)NBATCH * OUT_F * IN_F];  // per-batch W_eff

// ---- helpers ---------------------------------------------------------------
static __device__ __forceinline__ void mma_f16(float d[4], const uint32_t a[4],
                                               const uint32_t b[2]) {
    asm volatile(
        "mma.sync.aligned.m16n8k16.row.col.f32.f16.f16.f32 "
        "{%0,%1,%2,%3}, {%4,%5,%6,%7}, {%8,%9}, {%0,%1,%2,%3};"
        : "+f"(d[0]), "+f"(d[1]), "+f"(d[2]), "+f"(d[3])
        : "r"(a[0]), "r"(a[1]), "r"(a[2]), "r"(a[3]), "r"(b[0]), "r"(b[1]));
}
static __device__ __forceinline__ uint32_t smem_u32(const void* p) {
    uint32_t a;
    asm("{ .reg .u64 t; cvta.to.shared.u64 t, %1; cvt.u32.u64 %0, t; }"
        : "=r"(a) : "l"(p));
    return a;
}
static __device__ __forceinline__ void cpasync16(uint32_t dst, const void* src) {
    asm volatile("cp.async.cg.shared.global [%0], [%1], 16;"
                 :: "r"(dst), "l"(src) : "memory");
}
#define CP_COMMIT() asm volatile("cp.async.commit_group;" ::: "memory")
#define CP_WAIT1()  asm volatile("cp.async.wait_group 1;" ::: "memory")

// 256 threads load a 128x32 half tile (64 B/row = 4 x 16 B):
// kq = tid&3 (16B chunk), r0 = tid>>2 (0..63), rows r0 + 64*i.
static __device__ __forceinline__ void load_tile(uint32_t sdst,
                                                 const __half* __restrict__ src,
                                                 int ld, int row0, int k0,
                                                 int tid) {
    const int kq = tid & 3, r0 = tid >> 2;
    const __half* gp = src + (size_t)(row0 + r0) * ld + k0 + kq * 8;
    uint32_t d = sdst + ((uint32_t)r0 * SPADW + (uint32_t)kq * 4) * 4;
#pragma unroll
    for (int i = 0; i < 2; i++)
        cpasync16(d + i * (64 * SPADW * 4), gp + (size_t)(64 * i) * ld);
}

// ---- prologue: cvt x -> fp16, BmT repack, A transpose ----------------------
#define N4X (M_TOT * IN_F / 4)
#define NBMT (OUT_F * ERDIM)
#define NATH (IN_F * ERDIM)

__global__ void prep_kernel(const float* __restrict__ x,
                            const float* __restrict__ Bm,
                            const float* __restrict__ A) {
    const int stride = gridDim.x * blockDim.x;
    for (int i = blockIdx.x * blockDim.x + threadIdx.x; i < N4X; i += stride) {
        float4 v = ((const float4*)x)[i];
        __half2 h0 = __floats2half2_rn(v.x, v.y);
        __half2 h1 = __floats2half2_rn(v.z, v.w);
        uint2 u;
        u.x = *(uint32_t*)&h0; u.y = *(uint32_t*)&h1;
        *(uint2*)(g_xh + 4 * (size_t)i) = u;
    }
    for (int i = blockIdx.x * blockDim.x + threadIdx.x; i < NBMT; i += stride) {
        int o = i >> 7, j = i & 127;
        int e = j >> 4, r = j & 15;
        g_BmTh[i] = __float2half_rn(Bm[((size_t)e * OUT_F + o) * NR + r]);
    }
    for (int i = blockIdx.x * blockDim.x + threadIdx.x; i < NATH; i += stride) {
        int ii = i >> 7, j = i & 127;            // ATh[ii][j] = A[j][ii]
        g_ATh[i] = __float2half_rn(A[(size_t)j * IN_F + ii]);
    }
}

// ---- weff kernel: W_eff[b] = W + (SCALING*gate[b] ⊙ BmT) @ A ---------------
// grid (IN_F/128, OUT_F/128, NBATCH), block 256, full K=128 in smem.
__global__ __launch_bounds__(256)
void weff_kernel(const float* __restrict__ W, const float* __restrict__ z,
                 const float* __restrict__ Wg, const float* __restrict__ bg) {
    extern __shared__ uint32_t smem[];
    uint32_t* Gm = smem;                        // [128][WE_SPADW]
    uint32_t* At = smem + WE_TILE_WORDS;
    __shared__ float gsl[NE];

    const int tid = threadIdx.x, warp = tid >> 5, lane = tid & 31;
    const int wm = warp >> 2, wn = warp & 3;    // warp tile 64x32
    const int g = lane >> 2, t = lane & 3;
    const int n0 = blockIdx.x * 128;            // i-dim (IN_F)
    const int m0 = blockIdx.y * 128;            // o-dim (OUT_F)
    const int b = blockIdx.z;

    // gate softmax for this batch (redundant per CTA; trivial)
    if (tid < NE) {
        float s = bg[tid];
#pragma unroll
        for (int q = 0; q < GD; q++) s += z[b * GD + q] * Wg[tid * GD + q];
        gsl[tid] = s;
    }
    __syncthreads();
    if (tid == 0) {
        float mx = -1e30f;
        for (int k = 0; k < NE; k++) mx = fmaxf(mx, gsl[k]);
        float ex[NE]; float den = 0.f;
        for (int k = 0; k < NE; k++) { ex[k] = expf(gsl[k] - mx); den += ex[k]; }
        float inv = SCALING / den;
        for (int k = 0; k < NE; k++) gsl[k] = ex[k] * inv;
    }
    __syncthreads();

    // load tiles: thread (r = tid>>4, c = tid&15), rows r+16*i
    const int c = tid & 15, r = tid >> 4;
    const float gsc = gsl[c >> 1];              // 16B chunk of 8 j's = one expert
#pragma unroll
    for (int i = 0; i < 8; i++) {
        const int row = r + 16 * i;
        // gated BmT tile (rows = o)
        uint4 u = *(const uint4*)(g_BmTh + (size_t)(m0 + row) * ERDIM + c * 8);
        __half2* hp = (__half2*)&u;
#pragma unroll
        for (int k = 0; k < 4; k++) {
            float2 f = __half22float2(hp[k]);
            hp[k] = __floats2half2_rn(f.x * gsc, f.y * gsc);
        }
        *(uint4*)(Gm + (size_t)row * WE_SPADW + c * 4) = u;
        // A^T tile (rows = i)
        uint4 v = *(const uint4*)(g_ATh + (size_t)(n0 + row) * ERDIM + c * 8);
        *(uint4*)(At + (size_t)row * WE_SPADW + c * 4) = v;
    }
    __syncthreads();

    float acc[4][4][4];
#pragma unroll
    for (int i = 0; i < 4; i++)
#pragma unroll
        for (int j = 0; j < 4; j++)
#pragma unroll
            for (int q = 0; q < 4; q++) acc[i][j][q] = 0.f;

#pragma unroll
    for (int kk = 0; kk < 8; kk++) {            // 8 x k16 over K=128
        const int kb = kk * 8;
        uint32_t af[4][4], bf[4][2];
#pragma unroll
        for (int mi = 0; mi < 4; mi++) {
            const int m = wm * 64 + mi * 16 + g;
            af[mi][0] = Gm[m * WE_SPADW + kb + t];
            af[mi][1] = Gm[(m + 8) * WE_SPADW + kb + t];
            af[mi][2] = Gm[m * WE_SPADW + kb + t + 4];
            af[mi][3] = Gm[(m + 8) * WE_SPADW + kb + t + 4];
        }
#pragma unroll
        for (int ni = 0; ni < 4; ni++) {
            const int n = wn * 32 + ni * 8 + g;
            bf[ni][0] = At[n * WE_SPADW + kb + t];
            bf[ni][1] = At[n * WE_SPADW + kb + t + 4];
        }
#pragma unroll
        for (int mi = 0; mi < 4; mi++)
#pragma unroll
            for (int ni = 0; ni < 4; ni++)
                mma_f16(acc[mi][ni], af[mi], bf[ni]);
    }

    // epilogue: W_eff = delta + W (fp32 read), round to fp16
    __half* Wb = g_Weff + (size_t)b * OUT_F * IN_F;
#pragma unroll
    for (int mi = 0; mi < 4; mi++) {
        const int o = m0 + wm * 64 + mi * 16 + g;
#pragma unroll
        for (int ni = 0; ni < 4; ni++) {
            const int col = n0 + wn * 32 + ni * 8 + 2 * t;
            const float2 w0 = *(const float2*)(W + (size_t)o * IN_F + col);
            const float2 w1 = *(const float2*)(W + (size_t)(o + 8) * IN_F + col);
            __half2 h0 = __floats2half2_rn(acc[mi][ni][0] + w0.x, acc[mi][ni][1] + w0.y);
            __half2 h1 = __floats2half2_rn(acc[mi][ni][2] + w1.x, acc[mi][ni][3] + w1.y);
            *(__half2*)(Wb + (size_t)o * IN_F + col) = h0;
            *(__half2*)(Wb + (size_t)(o + 8) * IN_F + col) = h1;
        }
    }
}

// ---- main kernel: out = xh @ W_eff[b]^T + bias, 128x128, warp 64x32 --------
__global__ __launch_bounds__(256, 2)
void main_mma_kernel(const float* __restrict__ bias, float* __restrict__ out) {
    extern __shared__ uint32_t smem[];
    const uint32_t sb = smem_u32(smem);
    const int tid = threadIdx.x, warp = tid >> 5, lane = tid & 31;
    const int wm = warp >> 2, wn = warp & 3;
    const int g = lane >> 2, t = lane & 3;
    const int m0 = blockIdx.y * 128, n0 = blockIdx.x * 128;
    const __half* Wb = g_Weff + (size_t)(m0 >> 11) * OUT_F * IN_F;

    float acc[4][4][4];
#pragma unroll
    for (int i = 0; i < 4; i++)
#pragma unroll
        for (int j = 0; j < 4; j++)
#pragma unroll
            for (int r = 0; r < 4; r++) acc[i][j][r] = 0.f;

    const int T = IN_F / BK;   // 24
#pragma unroll
    for (int s = 0; s < 2; s++) {
        load_tile(sb + s * (TILE_WORDS * 4), g_xh, IN_F, m0, s * BK, tid);
        load_tile(sb + (NSTAGE + s) * (TILE_WORDS * 4), Wb, IN_F, n0, s * BK, tid);
        CP_COMMIT();
    }
    for (int tt = 0; tt < T; tt++) {
        CP_WAIT1();
        __syncthreads();
        const int ts = tt + 2;
        if (ts < T) {
            const int s = ts % NSTAGE;
            load_tile(sb + s * (TILE_WORDS * 4), g_xh, IN_F, m0, ts * BK, tid);
            load_tile(sb + (NSTAGE + s) * (TILE_WORDS * 4), Wb, IN_F, n0, ts * BK, tid);
        }
        CP_COMMIT();
        const int cc = tt % NSTAGE;
        const uint32_t* As = smem + cc * TILE_WORDS;
        const uint32_t* Bs = smem + (NSTAGE + cc) * TILE_WORDS;
#pragma unroll
        for (int kk = 0; kk < 2; kk++) {
            const int kb = kk * 8;
            uint32_t af[4][4], bf[4][2];
#pragma unroll
            for (int mi = 0; mi < 4; mi++) {
                const int m = wm * 64 + mi * 16 + g;
                af[mi][0] = As[m * SPADW + kb + t];
                af[mi][1] = As[(m + 8) * SPADW + kb + t];
                af[mi][2] = As[m * SPADW + kb + t + 4];
                af[mi][3] = As[(m + 8) * SPADW + kb + t + 4];
            }
#pragma unroll
            for (int ni = 0; ni < 4; ni++) {
                const int n = wn * 32 + ni * 8 + g;
                bf[ni][0] = Bs[n * SPADW + kb + t];
                bf[ni][1] = Bs[n * SPADW + kb + t + 4];
            }
#pragma unroll
            for (int mi = 0; mi < 4; mi++)
#pragma unroll
                for (int ni = 0; ni < 4; ni++)
                    mma_f16(acc[mi][ni], af[mi], bf[ni]);
        }
    }

#pragma unroll
    for (int mi = 0; mi < 4; mi++) {
        const int row = m0 + wm * 64 + mi * 16 + g;
#pragma unroll
        for (int ni = 0; ni < 4; ni++) {
            const int col = n0 + wn * 32 + ni * 8 + 2 * t;
            const float2 bb = *(const float2*)(bias + col);
            float2 v0 = make_float2(acc[mi][ni][0] + bb.x, acc[mi][ni][1] + bb.y);
            float2 v1 = make_float2(acc[mi][ni][2] + bb.x, acc[mi][ni][3] + bb.y);
            *(float2*)(out + (size_t)row * OUT_F + col) = v0;
            *(float2*)(out + (size_t)(row + 8) * OUT_F + col) = v1;
        }
    }
}

// ---------------------------------------------------------------------------
extern "C" void kernel_launch(void* const* d_in, const int* in_sizes, int n_in,
                              void* d_out, int out_size) {
    const float* x  = (const float*)d_in[0];   // [8,2048,768]
    const float* z  = (const float*)d_in[1];   // [8,64]
    const float* W  = (const float*)d_in[2];   // [2304,768]
    const float* b  = (const float*)d_in[3];   // [2304]
    const float* A  = (const float*)d_in[4];   // [8,16,768]
    const float* Bm = (const float*)d_in[5];   // [8,2304,16]
    const float* Wg = (const float*)d_in[6];   // [8,64]
    const float* bg = (const float*)d_in[7];   // [8]
    float* out = (float*)d_out;                // [8,2048,2304]

    // idempotent, capture-safe attribute setup (no static guards per harness rules)
    cudaFuncSetAttribute(weff_kernel,
                         cudaFuncAttributeMaxDynamicSharedMemorySize, WE_SMEM_BYTES);
    cudaFuncSetAttribute(main_mma_kernel,
                         cudaFuncAttributeMaxDynamicSharedMemorySize, SMEM_BYTES);

    // 1) fp16 conversion of x, BmT repack, A transpose
    prep_kernel<<<1184, 1024>>>(x, Bm, A);

    // 2) per-batch effective weights: W_eff[b] = W + (SCALING*gate ⊙ BmT) @ A
    weff_kernel<<<dim3(IN_F / 128, OUT_F / 128, NBATCH), 256, WE_SMEM_BYTES>>>(
        W, z, Wg, bg);

    // 3) single GEMM: out = x @ W_eff[b]^T + bias  (K=768)
    main_mma_kernel<<<dim3(OUT_F / 128, M_TOT / 128), 256, SMEM_BYTES>>>(b, out);
}